// round 6
// baseline (speedup 1.0000x reference)
#include <cuda_runtime.h>
#include <float.h>

#define Bq 8
#define Nq 6
#define Mq 64
#define Vq 32000
#define Tq 8
#define NS 7                   // Nq+1 template slots
#define MV (Mq * Vq)
#define MV2 (MV / 2)           // float2 stride between n-planes
#define V2 (Vq / 2)            // 16000 float2 per row
#define V4 (Vq / 4)
#define CHK 4                  // v-chunks per (b,m) row
#define C2 (V2 / CHK)          // 4000 float2 per chunk
#define NIT ((C2 + 256 - 1) / 256)   // 16 stage slots
#define TPB 256

// scratch (no allocs allowed)
__device__ float g_pmax[Bq * Mq * CHK][Tq];  // per-task partial max per t
__device__ float g_out0[Bq * Mq][Tq];        // out[b,t,m,v=0] (pad included at m==0)

union PU { unsigned long long u; float2 f; };
union XU { float4 f4; float f[4]; };

__device__ __forceinline__ unsigned long long fma2(unsigned long long a,
                                                   unsigned long long b,
                                                   unsigned long long c)
{
    unsigned long long d;
    asm("fma.rn.f32x2 %0, %1, %2, %3;" : "=l"(d) : "l"(a), "l"(b), "l"(c));
    return d;
}

// ---------------------------------------------------------------------------
// K1: one block per (b,m,chunk). Triple-buffered float2 stream (prefetch
// distance 2 -> ~12 LDGs outstanding per warp through the fma bursts).
// ---------------------------------------------------------------------------
__global__ __launch_bounds__(TPB, 2)
void k_pass1(const float* __restrict__ X,
             const float* __restrict__ tmplt,
             const int*   __restrict__ spans,
             float*       __restrict__ out)
{
    const int task = blockIdx.x;
    const int b = task >> 8;          // Mq*CHK = 256 tasks per batch
    const int m = (task >> 2) & 63;
    const int c = task & 3;
    const int tid = threadIdx.x;

    __shared__ float sw[Tq][NS];
    __shared__ float s_red[8][Tq];

    if (tid < Tq * NS) {
        const float val = tmplt[b * Tq * NS + tid];
        sw[tid / NS][tid % NS] = ((tid % NS) <= spans[b]) ? val : 0.0f;
    }
    __syncthreads();

    // weights packed over t-pairs: w2[tp][n] = (w[2tp][n], w[2tp+1][n])
    PU w2[4][Nq];
#pragma unroll
    for (int tp = 0; tp < 4; tp++)
#pragma unroll
        for (int n = 0; n < Nq; n++) {
            w2[tp][n].f.x = sw[2 * tp][n + 1];
            w2[tp][n].f.y = sw[2 * tp + 1][n + 1];
        }

    const size_t base = (size_t)b * Nq * MV + (size_t)m * Vq;   // float units
    const float2* X2  = reinterpret_cast<const float2*>(X) + (base >> 1);
    float2*       o2  = reinterpret_cast<float2*>(out + (size_t)(b * Mq + m) * Vq);

    // pre-step: out0[t] (chunk 0 only)
    if (c == 0 && tid == 0) {
        float xv[Nq];
#pragma unroll
        for (int n = 0; n < Nq; n++) xv[n] = X[base + (size_t)n * MV];
#pragma unroll
        for (int t = 0; t < Tq; t++) {
            float o = 0.0f;
#pragma unroll
            for (int n = 0; n < Nq; n++) o = fmaf(sw[t][n + 1], xv[n], o);
            if (m == 0) o += sw[t][0];
            g_out0[b * Mq + m][t] = o;
        }
    }

    float tmax[Tq];
#pragma unroll
    for (int t = 0; t < Tq; t++) tmax[t] = -FLT_MAX;

    const int i0   = c * C2 + tid;
    const int iend = (c + 1) * C2;

    float2 x0[Nq], x1[Nq], x2[Nq];

#define LOADS(buf, idx)                                                        \
    do { const int _i = (idx);                                                 \
         if (_i < iend) {                                                      \
             _Pragma("unroll")                                                 \
             for (int n = 0; n < Nq; n++) buf[n] = __ldcs(X2 + n * MV2 + _i);  \
         } } while (0)

#define COMPUTE(buf, idx)                                                      \
    do { const int _i = (idx);                                                 \
         if (_i < iend) {                                                      \
             float ox, oy;                                                     \
             _Pragma("unroll")                                                 \
             for (int j = 0; j < 2; j++) {                                     \
                 PU acc[4];                                                    \
                 _Pragma("unroll")                                             \
                 for (int tp = 0; tp < 4; tp++) acc[tp].u = 0ull;              \
                 _Pragma("unroll")                                             \
                 for (int n = 0; n < Nq; n++) {                                \
                     PU xx; const float s = j ? buf[n].y : buf[n].x;           \
                     xx.f.x = s; xx.f.y = s;                                   \
                     _Pragma("unroll")                                         \
                     for (int tp = 0; tp < 4; tp++)                            \
                         acc[tp].u = fma2(xx.u, w2[tp][n].u, acc[tp].u);       \
                 }                                                             \
                 _Pragma("unroll")                                             \
                 for (int tp = 0; tp < 4; tp++) {                              \
                     tmax[2 * tp]     = fmaxf(tmax[2 * tp],     acc[tp].f.x);  \
                     tmax[2 * tp + 1] = fmaxf(tmax[2 * tp + 1], acc[tp].f.y);  \
                 }                                                             \
                 if (j == 0) ox = acc[0].f.x; else oy = acc[0].f.x;            \
             }                                                                 \
             float2 o; o.x = ox; o.y = oy;                                     \
             __stcs(o2 + _i, o);                                               \
         } } while (0)

    // prologue: stages 0 and 1 (always valid: i0, i0+TPB < iend)
    LOADS(x0, i0);
    LOADS(x1, i0 + TPB);

#pragma unroll 1
    for (int k = 0; k < NIT; k += 3) {
        const int ic = i0 + k * TPB;
        LOADS(x2, ic + 2 * TPB);
        COMPUTE(x0, ic);
        LOADS(x0, ic + 3 * TPB);
        COMPUTE(x1, ic + TPB);
        LOADS(x1, ic + 4 * TPB);
        COMPUTE(x2, ic + 2 * TPB);
    }
#undef LOADS
#undef COMPUTE

    // pad one-hot on the speculative row: tid0 of (c==0,m==0) wrote v=0 itself
    if (c == 0 && m == 0 && tid == 0) {
        float2 v = __ldcg(o2);
        v.x += sw[0][0];
        __stcg(o2, v);
    }

    // block-reduce 8 maxes
    const int lane = tid & 31, wq = tid >> 5;
#pragma unroll
    for (int t = 0; t < Tq; t++) {
        float v = tmax[t];
#pragma unroll
        for (int off = 16; off; off >>= 1)
            v = fmaxf(v, __shfl_xor_sync(0xffffffffu, v, off));
        if (lane == 0) s_red[wq][t] = v;
    }
    __syncthreads();
    if (tid < Tq) {
        float mx = s_red[0][tid];
#pragma unroll
        for (int q = 1; q < 8; q++) mx = fmaxf(mx, s_red[q][tid]);
        g_pmax[task][tid] = mx;
    }
}

// ---------------------------------------------------------------------------
// K2: one block per batch. Builds the scan ONCE, then fixes only
// mispredicted rows (normally none).
// ---------------------------------------------------------------------------
__global__ __launch_bounds__(TPB) void k_fix(const float* __restrict__ X,
                                             const float* __restrict__ tmplt,
                                             const int*   __restrict__ spans,
                                             float*       __restrict__ out)
{
    const int b   = blockIdx.x;
    const int tid = threadIdx.x;

    __shared__ int                s_bits[Mq];
    __shared__ unsigned long long s_mask[Tq];
    __shared__ int                s_rowmap[Mq];

    if (tid < Mq) s_bits[tid] = 0;
    __syncthreads();

    for (int mt = tid; mt < Mq * Tq; mt += TPB) {      // 2 per thread
        const int mm = mt >> 3, t = mt & 7;
        float mx = -FLT_MAX;
#pragma unroll
        for (int cc = 0; cc < CHK; cc++)
            mx = fmaxf(mx, g_pmax[(b * Mq + mm) * CHK + cc][t]);
        // argmax_v==0  <=>  out0(padded) >= raw max (pad weight >= 0; ties -> 0)
        if (g_out0[b * Mq + mm][t] >= mx) atomicOr(&s_bits[mm], 1 << t);
    }
    __syncthreads();

    if (tid < Tq) {
        unsigned long long mk = 0ull;
        for (int mm = 0; mm < Mq; mm++)
            if ((s_bits[mm] >> tid) & 1) mk |= (1ull << mm);
        s_mask[tid] = mk;
    }
    __syncthreads();

    if (tid == 0) {
        int idx = 0;
        for (int t = 0; t < Tq; t++) {
            const unsigned long long mk = s_mask[t];
            const int first = mk ? (__ffsll((long long)mk) - 1) : Mq;
            const int len = min(first, Mq - idx);
            for (int q = idx; q < idx + len; q++)
                s_rowmap[q] = (t << 8) | (q - idx);
            idx += len;
        }
        for (int q = idx; q < Mq; q++) s_rowmap[q] = -1;
    }
    __syncthreads();

    // fix mispredicted rows (rare path)
    for (int p = 0; p < Mq; p++) {
        const int rm = s_rowmap[p];
        if (rm == p) continue;              // speculation (t=0, mloc=p) exact

        float* row = out + (size_t)(b * Mq + p) * Vq;

        if (rm < 0) {                       // never written in reference -> zeros
            const float4 z = make_float4(0.f, 0.f, 0.f, 0.f);
            for (int i4 = tid; i4 < V4; i4 += TPB)
                reinterpret_cast<float4*>(row)[i4] = z;
            continue;
        }

        const int t = rm >> 8, mloc = rm & 255;
        float wv[NS];
#pragma unroll
        for (int s = 0; s < NS; s++) {
            const float val = tmplt[b * Tq * NS + t * NS + s];
            wv[s] = (s <= spans[b]) ? val : 0.0f;
        }
        const size_t fb = (size_t)b * Nq * MV + (size_t)mloc * Vq;
        for (int i4 = tid; i4 < V4; i4 += TPB) {
            const int v = i4 * 4;
            XU x[Nq]; XU o;
#pragma unroll
            for (int n = 0; n < Nq; n++)
                x[n].f4 = *reinterpret_cast<const float4*>(X + fb + (size_t)n * MV + v);
#pragma unroll
            for (int j = 0; j < 4; j++) {
                float acc = 0.0f;
#pragma unroll
                for (int n = 0; n < Nq; n++) acc = fmaf(wv[n + 1], x[n].f[j], acc);
                o.f[j] = acc;
            }
            if (i4 == 0 && mloc == 0) o.f[0] += wv[0];
            *reinterpret_cast<float4*>(row + v) = o.f4;
        }
    }
}

extern "C" void kernel_launch(void* const* d_in, const int* in_sizes, int n_in,
                              void* d_out, int out_size)
{
    const float* X     = (const float*)d_in[0];
    const float* tmplt = (const float*)d_in[1];
    const int*   spans = (const int*)d_in[2];
    float*       out   = (float*)d_out;

    k_pass1<<<Bq * Mq * CHK, TPB>>>(X, tmplt, spans, out);
    k_fix<<<Bq, TPB>>>(X, tmplt, spans, out);
}

// round 8
// speedup vs baseline: 2.6923x; 2.6923x over previous
#include <cuda_runtime.h>
#include <stdint.h>
#include <float.h>

#define Bq 8
#define Nq 6
#define Mq 64
#define Vq 32000
#define Tq 8
#define NS 7                   // Nq+1 template slots
#define MV (Mq * Vq)
#define MV2 (MV / 2)           // float2 stride between n-planes
#define V2 (Vq / 2)            // 16000 float2 per row
#define V4 (Vq / 4)
#define CHK 4                  // v-chunks per (b,m) row
#define C2 (V2 / CHK)          // 4000 float2 per chunk
#define NIT 16                 // ceil(C2 / TPB) stage slots (last partially full)
#define TPB 256
#define NSTG 3                 // cp.async pipeline stages

// scratch (no allocs allowed)
__device__ float g_pmax[Bq * Mq * CHK][Tq];  // per-task partial max per t
__device__ float g_out0[Bq * Mq][Tq];        // out[b,t,m,v=0] (pad included at m==0)

union PU { unsigned long long u; float2 f; };
union XU { float4 f4; float f[4]; };

__device__ __forceinline__ unsigned long long fma2(unsigned long long a,
                                                   unsigned long long b,
                                                   unsigned long long c)
{
    unsigned long long d;
    asm("fma.rn.f32x2 %0, %1, %2, %3;" : "=l"(d) : "l"(a), "l"(b), "l"(c));
    return d;
}

__device__ __forceinline__ void cp_async8(const void* smem_ptr, const void* gaddr)
{
    unsigned int saddr = (unsigned int)__cvta_generic_to_shared(smem_ptr);
    asm volatile("cp.async.ca.shared.global [%0], [%1], 8;" :: "r"(saddr), "l"(gaddr));
}
#define CP_COMMIT()  asm volatile("cp.async.commit_group;")
#define CP_WAIT(n)   asm volatile("cp.async.wait_group %0;" :: "n"(n))

// ---------------------------------------------------------------------------
// K1: one block per (b,m,chunk). X staged through smem via cp.async, 3 stages
// deep, thread-private slots (no __syncthreads in the pipeline: thread tid
// only reads slots it filled itself; per-thread wait_group ordering suffices,
// and stage-reuse WAR is safe because the LDS issues before the refill
// cp.async is committed in program order on the same thread).
// ---------------------------------------------------------------------------
__global__ __launch_bounds__(TPB, 2)
void k_pass1(const float* __restrict__ X,
             const float* __restrict__ tmplt,
             const int*   __restrict__ spans,
             float*       __restrict__ out)
{
    const int task = blockIdx.x;
    const int b = task >> 8;          // Mq*CHK = 256 tasks per batch
    const int m = (task >> 2) & 63;
    const int c = task & 3;
    const int tid = threadIdx.x;

    __shared__ float2 stage[NSTG][Nq][TPB];   // 36.9 KB
    __shared__ float  sw[Tq][NS];
    __shared__ float  s_red[8][Tq];

    if (tid < Tq * NS) {
        const float val = tmplt[b * Tq * NS + tid];
        sw[tid / NS][tid % NS] = ((tid % NS) <= spans[b]) ? val : 0.0f;
    }
    __syncthreads();

    // weights packed over t-pairs: w2[tp][n] = (w[2tp][n], w[2tp+1][n])
    PU w2[4][Nq];
#pragma unroll
    for (int tp = 0; tp < 4; tp++)
#pragma unroll
        for (int n = 0; n < Nq; n++) {
            w2[tp][n].f.x = sw[2 * tp][n + 1];
            w2[tp][n].f.y = sw[2 * tp + 1][n + 1];
        }

    const size_t base = (size_t)b * Nq * MV + (size_t)m * Vq;   // float units
    const float2* X2  = reinterpret_cast<const float2*>(X) + (base >> 1);
    float2*       o2  = reinterpret_cast<float2*>(out + (size_t)(b * Mq + m) * Vq);

    // pre-step: out0[t] (chunk 0 only)
    if (c == 0 && tid == 0) {
        float xv[Nq];
#pragma unroll
        for (int n = 0; n < Nq; n++) xv[n] = X[base + (size_t)n * MV];
#pragma unroll
        for (int t = 0; t < Tq; t++) {
            float o = 0.0f;
#pragma unroll
            for (int n = 0; n < Nq; n++) o = fmaf(sw[t][n + 1], xv[n], o);
            if (m == 0) o += sw[t][0];
            g_out0[b * Mq + m][t] = o;
        }
    }

    float tmax[Tq];
#pragma unroll
    for (int t = 0; t < Tq; t++) tmax[t] = -FLT_MAX;

    const int i0   = c * C2;
    const int iend = (c + 1) * C2;

    // ISSUE stage s from slot k: thread-private destination [s][n][tid].
#define ISSUE(s, k)                                                            \
    do { const int _i = i0 + (k) * TPB + tid;                                  \
         if (_i < iend) {                                                      \
             _Pragma("unroll")                                                 \
             for (int n = 0; n < Nq; n++)                                      \
                 cp_async8(&stage[s][n][tid], X2 + n * MV2 + _i);              \
         }                                                                     \
         CP_COMMIT();                                                          \
    } while (0)

#define COMPUTE(s, k)                                                          \
    do { CP_WAIT(NSTG - 1);                                                    \
         const int _i = i0 + (k) * TPB + tid;                                  \
         if (_i < iend) {                                                      \
             float2 xb[Nq];                                                    \
             _Pragma("unroll")                                                 \
             for (int n = 0; n < Nq; n++) xb[n] = stage[s][n][tid];            \
             float ox, oy;                                                     \
             _Pragma("unroll")                                                 \
             for (int j = 0; j < 2; j++) {                                     \
                 PU acc[4];                                                    \
                 _Pragma("unroll")                                             \
                 for (int tp = 0; tp < 4; tp++) acc[tp].u = 0ull;              \
                 _Pragma("unroll")                                             \
                 for (int n = 0; n < Nq; n++) {                                \
                     PU xx; const float sgl = j ? xb[n].y : xb[n].x;           \
                     xx.f.x = sgl; xx.f.y = sgl;                               \
                     _Pragma("unroll")                                         \
                     for (int tp = 0; tp < 4; tp++)                            \
                         acc[tp].u = fma2(xx.u, w2[tp][n].u, acc[tp].u);       \
                 }                                                             \
                 _Pragma("unroll")                                             \
                 for (int tp = 0; tp < 4; tp++) {                              \
                     tmax[2 * tp]     = fmaxf(tmax[2 * tp],     acc[tp].f.x);  \
                     tmax[2 * tp + 1] = fmaxf(tmax[2 * tp + 1], acc[tp].f.y);  \
                 }                                                             \
                 if (j == 0) ox = acc[0].f.x; else oy = acc[0].f.x;            \
             }                                                                 \
             float2 o; o.x = ox; o.y = oy;                                     \
             __stcs(o2 + _i, o);                                               \
         }                                                                     \
    } while (0)

    // prologue: fill all 3 stages
    ISSUE(0, 0);
    ISSUE(1, 1);
    ISSUE(2, 2);

#pragma unroll 1
    for (int k = 0; k < NIT; k += NSTG) {
        COMPUTE(0, k);     ISSUE(0, k + 3);
        COMPUTE(1, k + 1); ISSUE(1, k + 4);
        COMPUTE(2, k + 2); ISSUE(2, k + 5);
    }
    CP_WAIT(0);
#undef ISSUE
#undef COMPUTE

    // pad one-hot on the speculative row: tid0 of (c==0,m==0) wrote v=0 itself
    if (c == 0 && m == 0 && tid == 0) {
        float2 v = __ldcg(o2);
        v.x += sw[0][0];
        __stcg(o2, v);
    }

    // block-reduce 8 maxes
    const int lane = tid & 31, wq = tid >> 5;
#pragma unroll
    for (int t = 0; t < Tq; t++) {
        float v = tmax[t];
#pragma unroll
        for (int off = 16; off; off >>= 1)
            v = fmaxf(v, __shfl_xor_sync(0xffffffffu, v, off));
        if (lane == 0) s_red[wq][t] = v;
    }
    __syncthreads();
    if (tid < Tq) {
        float mx = s_red[0][tid];
#pragma unroll
        for (int q = 1; q < 8; q++) mx = fmaxf(mx, s_red[q][tid]);
        g_pmax[task][tid] = mx;
    }
}

// ---------------------------------------------------------------------------
// K2 (R5-proven): one block per (b,p). Rebuilds the scan in-block (cheap,
// L2 broadcast), then fixes this row only if the t=0 speculation was wrong.
// ---------------------------------------------------------------------------
__global__ __launch_bounds__(TPB) void k_fix(const float* __restrict__ X,
                                             const float* __restrict__ tmplt,
                                             const int*   __restrict__ spans,
                                             float*       __restrict__ out)
{
    const int bx  = blockIdx.x;
    const int b   = bx >> 6;
    const int p   = bx & 63;
    const int tid = threadIdx.x;

    __shared__ int                s_bits[Mq];
    __shared__ unsigned long long s_mask[Tq];
    __shared__ int                s_rowmap[Mq];

    if (tid < Mq) s_bits[tid] = 0;
    __syncthreads();

    for (int mt = tid; mt < Mq * Tq; mt += TPB) {      // 2 per thread
        const int mm = mt >> 3, t = mt & 7;
        float mx = -FLT_MAX;
#pragma unroll
        for (int cc = 0; cc < CHK; cc++)
            mx = fmaxf(mx, g_pmax[(b * Mq + mm) * CHK + cc][t]);
        // argmax_v==0  <=>  out0(padded) >= raw max (pad weight >= 0; ties -> 0)
        if (g_out0[b * Mq + mm][t] >= mx) atomicOr(&s_bits[mm], 1 << t);
    }
    __syncthreads();

    if (tid < Tq) {
        unsigned long long mk = 0ull;
        for (int mm = 0; mm < Mq; mm++)
            if ((s_bits[mm] >> tid) & 1) mk |= (1ull << mm);
        s_mask[tid] = mk;
    }
    __syncthreads();

    if (tid == 0) {
        int idx = 0;
        for (int t = 0; t < Tq; t++) {
            const unsigned long long mk = s_mask[t];
            const int first = mk ? (__ffsll((long long)mk) - 1) : Mq;
            const int len = min(first, Mq - idx);
            for (int q = idx; q < idx + len; q++)
                s_rowmap[q] = (t << 8) | (q - idx);
            idx += len;
        }
        for (int q = idx; q < Mq; q++) s_rowmap[q] = -1;
    }
    __syncthreads();

    const int rm = s_rowmap[p];
    if (rm == p) return;                    // speculation (t=0, mloc=p) exact

    float* row = out + (size_t)(b * Mq + p) * Vq;

    if (rm < 0) {                           // never written in reference -> zeros
        const float4 z = make_float4(0.f, 0.f, 0.f, 0.f);
        for (int i4 = tid; i4 < V4; i4 += TPB)
            reinterpret_cast<float4*>(row)[i4] = z;
        return;
    }

    const int t = rm >> 8, mloc = rm & 255;
    float wv[NS];
#pragma unroll
    for (int s = 0; s < NS; s++) {
        const float val = tmplt[b * Tq * NS + t * NS + s];
        wv[s] = (s <= spans[b]) ? val : 0.0f;
    }
    const size_t fb = (size_t)b * Nq * MV + (size_t)mloc * Vq;
    for (int i4 = tid; i4 < V4; i4 += TPB) {
        const int v = i4 * 4;
        XU x[Nq]; XU o;
#pragma unroll
        for (int n = 0; n < Nq; n++)
            x[n].f4 = *reinterpret_cast<const float4*>(X + fb + (size_t)n * MV + v);
#pragma unroll
        for (int j = 0; j < 4; j++) {
            float acc = 0.0f;
#pragma unroll
            for (int n = 0; n < Nq; n++) acc = fmaf(wv[n + 1], x[n].f[j], acc);
            o.f[j] = acc;
        }
        if (i4 == 0 && mloc == 0) o.f[0] += wv[0];
        *reinterpret_cast<float4*>(row + v) = o.f4;
    }
}

extern "C" void kernel_launch(void* const* d_in, const int* in_sizes, int n_in,
                              void* d_out, int out_size)
{
    const float* X     = (const float*)d_in[0];
    const float* tmplt = (const float*)d_in[1];
    const int*   spans = (const int*)d_in[2];
    float*       out   = (float*)d_out;

    k_pass1<<<Bq * Mq * CHK, TPB>>>(X, tmplt, spans, out);
    k_fix<<<Bq * Mq, TPB>>>(X, tmplt, spans, out);
}